// round 7
// baseline (speedup 1.0000x reference)
#include <cuda_runtime.h>
#include <cstdint>

constexpr int cB = 8192;
constexpr int cN = 40;
constexpr int cF = 256;
constexpr int cNBLK = 4;
constexpr int cBLK = 10;
constexpr long long cM = (long long)cB * cN;  // 327680 rows
constexpr float cEPS = 1e-5f;

// Scratch (device globals: allocation-free per harness rules).
// y lives in d_out — no second large buffer.
__device__ float g_z[(size_t)cM * cF];      // 335 MB: block-bmm result
__device__ float g_sum[cN * cF];
__device__ float g_sumsq[cN * cF];
__device__ float g_scale[cN * cF];
__device__ float g_bias[cN * cF];

// ---------------------------------------------------------------------------
// packed fp32x2 helpers (Blackwell): 2 FMAs per instruction
// ---------------------------------------------------------------------------
__device__ __forceinline__ unsigned long long pack2(float v) {
    unsigned long long r;
    asm("mov.b64 %0, {%1, %1};" : "=l"(r) : "f"(v));
    return r;
}
__device__ __forceinline__ void fma2(unsigned long long& d, unsigned long long a,
                                     unsigned long long b) {
    asm("fma.rn.f32x2 %0, %1, %2, %0;" : "+l"(d) : "l"(a), "l"(b));
}

// ---------------------------------------------------------------------------
// k_zero: clear the stat accumulators (graph replays must be idempotent)
// ---------------------------------------------------------------------------
__global__ void k_zero() {
    int i = blockIdx.x * blockDim.x + threadIdx.x;
    if (i < cN * cF) { g_sum[i] = 0.f; g_sumsq[i] = 0.f; }
}

// ---------------------------------------------------------------------------
// k_z: z[b, s+r, k] = sum_j adj[b, s+r, s+j] * input[b, s+j, k]
// One CTA per (batch, crop). Input rows staged in smem, read exactly once.
// ---------------------------------------------------------------------------
__global__ void __launch_bounds__(256) k_z(const float* __restrict__ inp,
                                           const float* __restrict__ adj) {
    const int b = blockIdx.x;
    const int s = blockIdx.y * cBLK;
    __shared__ float a[cBLK][cBLK];
    __shared__ float x[cBLK][cF];
    const int tid = threadIdx.x;

    if (tid < cBLK * cBLK)
        a[tid / cBLK][tid % cBLK] =
            adj[((size_t)b * cN + s + tid / cBLK) * cN + s + tid % cBLK];
    #pragma unroll
    for (int idx = tid; idx < cBLK * cF; idx += 256) {
        int j = idx >> 8, k = idx & 255;
        x[j][k] = inp[((size_t)b * cN + s + j) * cF + k];
    }
    __syncthreads();
    #pragma unroll
    for (int idx = tid; idx < cBLK * cF; idx += 256) {
        int r = idx >> 8, k = idx & 255;
        float acc = 0.f;
        #pragma unroll
        for (int j = 0; j < cBLK; j++) acc = fmaf(a[r][j], x[j][k], acc);
        g_z[((size_t)b * cN + s + r) * cF + k] = acc;
    }
}

// ---------------------------------------------------------------------------
// k_gemm: y = z @ W.  [327680 x 256] * [256 x 256], y written to d_out.
// 128x128 CTA tile, 256 threads, 8x8 microtile per thread. Register-prefetch
// double buffering: next k-tile's gmem loads issue before computing on the
// current smem tile, hiding DRAM latency inside the FFMA2 work.
// A fragment read as 2x LDS.128 (broadcast), B as 4x LDS.64 conflict-free.
// ---------------------------------------------------------------------------
__global__ void __launch_bounds__(256) k_gemm(const float* __restrict__ Wm,
                                              float* __restrict__ y) {
    __shared__ float As[16][128];  // transposed A tile: As[k][m]
    __shared__ float Bs[16][128];  // Bs[k][n]
    const int tid = threadIdx.x;
    const size_t m0 = (size_t)blockIdx.x * 128;
    const int n0 = blockIdx.y * 128;
    const int tx = tid & 15;   // column group
    const int ty = tid >> 4;   // row group

    unsigned long long acc[8][4];
    #pragma unroll
    for (int r = 0; r < 8; r++)
        #pragma unroll
        for (int c = 0; c < 4; c++) acc[r][c] = 0ull;

    const int arow = tid >> 2, acol = (tid & 3) * 4;
    const int brow = tid >> 5, bcol = (tid & 31) * 4;

    // Prefetch k-tile 0 into registers.
    float4 av[2], bv[2];
    #pragma unroll
    for (int p = 0; p < 2; p++) {
        av[p] = *(const float4*)&g_z[(m0 + arow + p * 64) * cF + acol];
        bv[p] = *(const float4*)&Wm[(size_t)(brow + p * 8) * cF + n0 + bcol];
    }

    for (int k0 = 0; k0 < 256; k0 += 16) {
        // Store the prefetched tile to smem.
        #pragma unroll
        for (int p = 0; p < 2; p++) {
            As[acol + 0][arow + p * 64] = av[p].x;
            As[acol + 1][arow + p * 64] = av[p].y;
            As[acol + 2][arow + p * 64] = av[p].z;
            As[acol + 3][arow + p * 64] = av[p].w;
            *(float4*)&Bs[brow + p * 8][bcol] = bv[p];
        }
        __syncthreads();
        // Issue next tile's global loads (overlap with compute below).
        if (k0 + 16 < 256) {
            #pragma unroll
            for (int p = 0; p < 2; p++) {
                av[p] = *(const float4*)&g_z[(m0 + arow + p * 64) * cF + k0 + 16 + acol];
                bv[p] = *(const float4*)&Wm[(size_t)(k0 + 16 + brow + p * 8) * cF + n0 + bcol];
            }
        }
        #pragma unroll
        for (int k = 0; k < 16; k++) {
            unsigned long long bb[4];
            #pragma unroll
            for (int c = 0; c < 4; c++)
                bb[c] = *(const unsigned long long*)&Bs[k][tx * 2 + c * 32];
            // A fragment: 8 consecutive floats -> two LDS.128 (32B aligned)
            float4 a0 = *(const float4*)&As[k][ty * 8];
            float4 a1 = *(const float4*)&As[k][ty * 8 + 4];
            float aa[8] = {a0.x, a0.y, a0.z, a0.w, a1.x, a1.y, a1.z, a1.w};
            #pragma unroll
            for (int r = 0; r < 8; r++) {
                unsigned long long ap = pack2(aa[r]);
                #pragma unroll
                for (int c = 0; c < 4; c++) fma2(acc[r][c], ap, bb[c]);
            }
        }
        __syncthreads();  // protect smem before next store
    }
    #pragma unroll
    for (int r = 0; r < 8; r++) {
        size_t row = m0 + ty * 8 + r;
        #pragma unroll
        for (int c = 0; c < 4; c++)
            *(unsigned long long*)&y[row * cF + n0 + tx * 2 + c * 32] = acc[r][c];
    }
}

// ---------------------------------------------------------------------------
// k_stats: per-(n,f) sum and sum-of-squares over the batch dim.
// CTA = (batch slice of 256, n); thread owns one f; register partials then
// one atomicAdd per thread (655K spread atomics total).
// ---------------------------------------------------------------------------
__global__ void __launch_bounds__(256) k_stats(const float* __restrict__ y) {
    const int n = blockIdx.y;
    const int f = threadIdx.x;
    const size_t b0 = (size_t)blockIdx.x * 256;
    float s = 0.f, q = 0.f;
    #pragma unroll 4
    for (int b = 0; b < 256; b++) {
        float v = y[((b0 + b) * cN + n) * cF + f];
        s += v;
        q = fmaf(v, v, q);
    }
    atomicAdd(&g_sum[n * cF + f], s);
    atomicAdd(&g_sumsq[n * cF + f], q);
}

// ---------------------------------------------------------------------------
// k_finalize: fold BN into per-column scale/bias.
// out = (y - mean)*rsqrt(var+eps)*gamma_{n/10} + sum_i beta_i
//     = y*scale + bias
// ---------------------------------------------------------------------------
__global__ void k_finalize(const float* __restrict__ gamma,
                           const float* __restrict__ beta) {
    const int n = blockIdx.x, f = threadIdx.x;
    const int idx = n * cF + f;
    const float invB = 1.0f / (float)cB;
    float mean = g_sum[idx] * invB;
    float var = fmaf(-mean, mean, g_sumsq[idx] * invB);
    float inv = rsqrtf(var + cEPS);
    float g = gamma[(n / cBLK) * (cN * cF) + idx];
    float bs = beta[idx] + beta[cN * cF + idx] + beta[2 * cN * cF + idx] +
               beta[3 * cN * cF + idx];
    float sc = inv * g;
    g_scale[idx] = sc;
    g_bias[idx] = fmaf(-mean, sc, bs);
}

// ---------------------------------------------------------------------------
// k_norm: out = out*scale + bias, in place, float4 grid-stride.
// ---------------------------------------------------------------------------
__global__ void __launch_bounds__(256) k_norm(float* __restrict__ out) {
    const size_t total4 = (size_t)cM * cF / 4;
    float4* o4 = (float4*)out;
    for (size_t i = (size_t)blockIdx.x * blockDim.x + threadIdx.x; i < total4;
         i += (size_t)gridDim.x * blockDim.x) {
        int c = (int)(i % (size_t)(cN * cF / 4)) * 4;
        float4 v = o4[i];
        float4 r;
        r.x = fmaf(v.x, g_scale[c + 0], g_bias[c + 0]);
        r.y = fmaf(v.y, g_scale[c + 1], g_bias[c + 1]);
        r.z = fmaf(v.z, g_scale[c + 2], g_bias[c + 2]);
        r.w = fmaf(v.w, g_scale[c + 3], g_bias[c + 3]);
        o4[i] = r;
    }
}

// ---------------------------------------------------------------------------
extern "C" void kernel_launch(void* const* d_in, const int* in_sizes, int n_in,
                              void* d_out, int out_size) {
    const float* inp   = (const float*)d_in[0];  // [8192, 40, 256]
    const float* adj   = (const float*)d_in[1];  // [8192, 40, 40]
    const float* Wm    = (const float*)d_in[2];  // [256, 256]
    const float* gamma = (const float*)d_in[3];  // [4, 10240]
    const float* beta  = (const float*)d_in[4];  // [4, 10240]
    float* out = (float*)d_out;                  // [8192, 40, 256]

    k_zero<<<(cN * cF + 255) / 256, 256>>>();
    k_z<<<dim3(cB, cNBLK), 256>>>(inp, adj);
    k_gemm<<<dim3((unsigned)(cM / 128), 2), 256>>>(Wm, out);
    k_stats<<<dim3(32, cN), 256>>>(out);
    k_finalize<<<cN, cF>>>(gamma, beta);
    k_norm<<<20480, 256>>>(out);
}

// round 13
// speedup vs baseline: 1.6067x; 1.6067x over previous
#include <cuda_runtime.h>
#include <cuda_bf16.h>
#include <cstdint>

constexpr int cB = 8192;
constexpr int cN = 40;
constexpr int cF = 256;
constexpr int cNBLK = 4;
constexpr int cBLK = 10;
constexpr long long cM = (long long)cB * cN;  // 327680 rows
constexpr float cEPS = 1e-5f;

// Scratch (device globals: allocation-free per harness rules).
__device__ __nv_bfloat16 g_zh[(size_t)cM * cF];   // 167 MB: z hi split
__device__ __nv_bfloat16 g_zl[(size_t)cM * cF];   // 167 MB: z lo split
__device__ __nv_bfloat16 g_wth[cF * cF];          // W^T hi: [n][k]
__device__ __nv_bfloat16 g_wtl[cF * cF];          // W^T lo: [n][k]
__device__ float g_sum[cN * cF];
__device__ float g_sumsq[cN * cF];
__device__ float g_scale[cN * cF];
__device__ float g_bias[cN * cF];

// ---------------------------------------------------------------------------
// helpers
// ---------------------------------------------------------------------------
__device__ __forceinline__ uint32_t smem_to_u32(const void* p) {
    uint32_t a;
    asm("{ .reg .u64 t; cvta.to.shared.u64 t, %1; cvt.u32.u64 %0, t; }"
        : "=r"(a) : "l"(p));
    return a;
}
#define SMEM_SWIZZLE_128B(byte_offset) ((byte_offset) ^ (((byte_offset) >> 3) & 0x70))

__device__ __forceinline__ void ldm_x4(uint32_t* r, uint32_t addr) {
    asm volatile("ldmatrix.sync.aligned.m8n8.x4.shared.b16 {%0,%1,%2,%3}, [%4];"
                 : "=r"(r[0]), "=r"(r[1]), "=r"(r[2]), "=r"(r[3]) : "r"(addr));
}
__device__ __forceinline__ void mma16816(float* c, const uint32_t* a,
                                         uint32_t b0, uint32_t b1) {
    asm volatile(
        "mma.sync.aligned.m16n8k16.row.col.f32.bf16.bf16.f32 "
        "{%0,%1,%2,%3}, {%4,%5,%6,%7}, {%8,%9}, {%0,%1,%2,%3};"
        : "+f"(c[0]), "+f"(c[1]), "+f"(c[2]), "+f"(c[3])
        : "r"(a[0]), "r"(a[1]), "r"(a[2]), "r"(a[3]), "r"(b0), "r"(b1));
}
// ldmatrix x4 address for a 16row x 16col(bf16) block at (row0, ks*16) in a
// tile with 128-byte rows + SW128 swizzle.
__device__ __forceinline__ uint32_t frag_addr(uint32_t tile_base, int row0,
                                              int ks, int lane) {
    int row = row0 + (lane & 7) + ((lane >> 3) & 1) * 8;
    int c16 = ks * 2 + (lane >> 4);
    return tile_base + row * 128 + ((c16 ^ (row & 7)) * 16);
}

// ---------------------------------------------------------------------------
// k_zero: clear stat accumulators (graph replays must be idempotent)
// ---------------------------------------------------------------------------
__global__ void k_zero() {
    int i = blockIdx.x * blockDim.x + threadIdx.x;
    if (i < cN * cF) { g_sum[i] = 0.f; g_sumsq[i] = 0.f; }
}

// ---------------------------------------------------------------------------
// k_wprep: W[k][n] -> transposed bf16 hi/lo splits Wt[n][k]
// ---------------------------------------------------------------------------
__global__ void k_wprep(const float* __restrict__ W) {
    int n = blockIdx.x, k = threadIdx.x;
    float w = W[k * cF + n];
    __nv_bfloat16 hi = __float2bfloat16(w);
    __nv_bfloat16 lo = __float2bfloat16(w - __bfloat162float(hi));
    g_wth[n * cF + k] = hi;
    g_wtl[n * cF + k] = lo;
}

// ---------------------------------------------------------------------------
// k_z: z[b, s+r, k] = sum_j adj[b,s+r,s+j] * input[b,s+j,k], split to bf16
// hi/lo. One CTA per (batch, crop); input staged in smem, read once.
// ---------------------------------------------------------------------------
__global__ void __launch_bounds__(256) k_z(const float* __restrict__ inp,
                                           const float* __restrict__ adj) {
    const int b = blockIdx.x;
    const int s = blockIdx.y * cBLK;
    __shared__ float a[cBLK][cBLK];
    __shared__ float x[cBLK][cF];
    const int tid = threadIdx.x;

    if (tid < cBLK * cBLK)
        a[tid / cBLK][tid % cBLK] =
            adj[((size_t)b * cN + s + tid / cBLK) * cN + s + tid % cBLK];
    #pragma unroll
    for (int idx = tid; idx < cBLK * cF; idx += 256) {
        int j = idx >> 8, k = idx & 255;
        x[j][k] = inp[((size_t)b * cN + s + j) * cF + k];
    }
    __syncthreads();
    for (int idx = tid; idx < cBLK * (cF / 2); idx += 256) {
        int r = idx >> 7, k2 = (idx & 127) * 2;
        float acc0 = 0.f, acc1 = 0.f;
        #pragma unroll
        for (int j = 0; j < cBLK; j++) {
            acc0 = fmaf(a[r][j], x[j][k2], acc0);
            acc1 = fmaf(a[r][j], x[j][k2 + 1], acc1);
        }
        __nv_bfloat16 h0 = __float2bfloat16(acc0);
        __nv_bfloat16 h1 = __float2bfloat16(acc1);
        __nv_bfloat16 l0 = __float2bfloat16(acc0 - __bfloat162float(h0));
        __nv_bfloat16 l1 = __float2bfloat16(acc1 - __bfloat162float(h1));
        size_t off = ((size_t)b * cN + s + r) * cF + k2;
        __nv_bfloat162 hv; hv.x = h0; hv.y = h1;
        __nv_bfloat162 lv; lv.x = l0; lv.y = l1;
        *(__nv_bfloat162*)(g_zh + off) = hv;
        *(__nv_bfloat162*)(g_zl + off) = lv;
    }
}

// ---------------------------------------------------------------------------
// k_gemm_mma: y = z @ W via mma.sync bf16 3-pass split
//   (zh@Wh + zh@Wl + zl@Wh), fp32 accumulate.
// CTA: 128(M) x 128(N), 256 threads = 8 warps (2 M x 4 N), warp tile 64x32.
// K-loop: 4 chunks of 64; per chunk load A-hi/A-lo (128x64) + B-hi/B-lo
// (128x64, [n][k]) into SW128 smem; ldmatrix + 48 HMMA per warp per k16.
// ---------------------------------------------------------------------------
constexpr int SM_AH = 0;
constexpr int SM_AL = 16384;
constexpr int SM_BH = 32768;
constexpr int SM_BL = 49152;
constexpr int SMEM_MMA_BYTES = 65536;

__device__ __forceinline__ void load_tile64(char* dst, const __nv_bfloat16* src,
                                            size_t row_base, int k0, int tid) {
    #pragma unroll
    for (int idx = tid; idx < 1024; idx += 256) {
        int r = idx >> 3, c16 = idx & 7;
        uint4 v = *(const uint4*)(src + (row_base + r) * cF + k0 + c16 * 8);
        *(uint4*)(dst + SMEM_SWIZZLE_128B(r * 128 + c16 * 16)) = v;
    }
}

__global__ void __launch_bounds__(256) k_gemm_mma(float* __restrict__ y) {
    extern __shared__ __align__(128) char smem[];
    const uint32_t sb = smem_to_u32(smem);
    const int tid = threadIdx.x;
    const int wid = tid >> 5, lane = tid & 31;
    const int wm = wid & 1, wn = wid >> 1;  // warp grid 2(M) x 4(N)
    const size_t mbase = (size_t)blockIdx.x * 128;
    const int nbase = blockIdx.y * 128;

    float C[4][4][4];
    #pragma unroll
    for (int mt = 0; mt < 4; mt++)
        #pragma unroll
        for (int nt = 0; nt < 4; nt++)
            #pragma unroll
            for (int i = 0; i < 4; i++) C[mt][nt][i] = 0.f;

    for (int ci = 0; ci < 4; ci++) {
        const int k0 = ci * 64;
        if (ci > 0) __syncthreads();  // previous compute done before overwrite
        load_tile64(smem + SM_AH, g_zh, mbase, k0, tid);
        load_tile64(smem + SM_AL, g_zl, mbase, k0, tid);
        load_tile64(smem + SM_BH, g_wth, (size_t)nbase, k0, tid);
        load_tile64(smem + SM_BL, g_wtl, (size_t)nbase, k0, tid);
        __syncthreads();

        #pragma unroll
        for (int ks = 0; ks < 4; ks++) {
            uint32_t a[4][4], bh[2][4], bl[2][4];
            #pragma unroll
            for (int p = 0; p < 2; p++) {
                ldm_x4(bh[p], frag_addr(sb + SM_BH, wn * 32 + p * 16, ks, lane));
                ldm_x4(bl[p], frag_addr(sb + SM_BL, wn * 32 + p * 16, ks, lane));
            }
            // pass 1+2: A-hi against B-hi and B-lo
            #pragma unroll
            for (int mt = 0; mt < 4; mt++)
                ldm_x4(a[mt], frag_addr(sb + SM_AH, wm * 64 + mt * 16, ks, lane));
            #pragma unroll
            for (int mt = 0; mt < 4; mt++)
                #pragma unroll
                for (int nt = 0; nt < 4; nt++) {
                    int p = nt >> 1, q = nt & 1;
                    mma16816(C[mt][nt], a[mt], bh[p][q], bh[p][q + 2]);
                    mma16816(C[mt][nt], a[mt], bl[p][q], bl[p][q + 2]);
                }
            // pass 3: A-lo against B-hi
            #pragma unroll
            for (int mt = 0; mt < 4; mt++)
                ldm_x4(a[mt], frag_addr(sb + SM_AL, wm * 64 + mt * 16, ks, lane));
            #pragma unroll
            for (int mt = 0; mt < 4; mt++)
                #pragma unroll
                for (int nt = 0; nt < 4; nt++) {
                    int p = nt >> 1, q = nt & 1;
                    mma16816(C[mt][nt], a[mt], bh[p][q], bh[p][q + 2]);
                }
        }
    }

    // Epilogue: C fragment layout -> global. c0,c1 = (row, col..col+1);
    // c2,c3 = (row+8, col..col+1).
    #pragma unroll
    for (int mt = 0; mt < 4; mt++) {
        #pragma unroll
        for (int nt = 0; nt < 4; nt++) {
            size_t row = mbase + wm * 64 + mt * 16 + (lane >> 2);
            int col = nbase + wn * 32 + nt * 8 + (lane & 3) * 2;
            float2 v0 = make_float2(C[mt][nt][0], C[mt][nt][1]);
            float2 v1 = make_float2(C[mt][nt][2], C[mt][nt][3]);
            *(float2*)(y + row * cF + col) = v0;
            *(float2*)(y + (row + 8) * cF + col) = v1;
        }
    }
}

// ---------------------------------------------------------------------------
// k_stats: per-(n,f) sum / sum-of-squares over batch; spread atomics.
// ---------------------------------------------------------------------------
__global__ void __launch_bounds__(256) k_stats(const float* __restrict__ y) {
    const int n = blockIdx.y;
    const int f = threadIdx.x;
    const size_t b0 = (size_t)blockIdx.x * 128;
    float s = 0.f, q = 0.f;
    #pragma unroll 8
    for (int b = 0; b < 128; b++) {
        float v = y[((b0 + b) * cN + n) * cF + f];
        s += v;
        q = fmaf(v, v, q);
    }
    atomicAdd(&g_sum[n * cF + f], s);
    atomicAdd(&g_sumsq[n * cF + f], q);
}

// ---------------------------------------------------------------------------
// k_finalize: fold BN into per-column scale/bias.
// ---------------------------------------------------------------------------
__global__ void k_finalize(const float* __restrict__ gamma,
                           const float* __restrict__ beta) {
    const int n = blockIdx.x, f = threadIdx.x;
    const int idx = n * cF + f;
    const float invB = 1.0f / (float)cB;
    float mean = g_sum[idx] * invB;
    float var = fmaf(-mean, mean, g_sumsq[idx] * invB);
    float inv = rsqrtf(var + cEPS);
    float g = gamma[(n / cBLK) * (cN * cF) + idx];
    float bs = beta[idx] + beta[cN * cF + idx] + beta[2 * cN * cF + idx] +
               beta[3 * cN * cF + idx];
    float sc = inv * g;
    g_scale[idx] = sc;
    g_bias[idx] = fmaf(-mean, sc, bs);
}

// ---------------------------------------------------------------------------
// k_norm: out = out*scale + bias, in place, float4 grid-stride.
// ---------------------------------------------------------------------------
__global__ void __launch_bounds__(256) k_norm(float* __restrict__ out) {
    const size_t total4 = (size_t)cM * cF / 4;
    float4* o4 = (float4*)out;
    for (size_t i = (size_t)blockIdx.x * blockDim.x + threadIdx.x; i < total4;
         i += (size_t)gridDim.x * blockDim.x) {
        int c = (int)(i % (size_t)(cN * cF / 4)) * 4;
        float4 v = o4[i];
        float4 r;
        r.x = fmaf(v.x, g_scale[c + 0], g_bias[c + 0]);
        r.y = fmaf(v.y, g_scale[c + 1], g_bias[c + 1]);
        r.z = fmaf(v.z, g_scale[c + 2], g_bias[c + 2]);
        r.w = fmaf(v.w, g_scale[c + 3], g_bias[c + 3]);
        o4[i] = r;
    }
}

// ---------------------------------------------------------------------------
extern "C" void kernel_launch(void* const* d_in, const int* in_sizes, int n_in,
                              void* d_out, int out_size) {
    const float* inp   = (const float*)d_in[0];  // [8192, 40, 256]
    const float* adj   = (const float*)d_in[1];  // [8192, 40, 40]
    const float* Wm    = (const float*)d_in[2];  // [256, 256]
    const float* gamma = (const float*)d_in[3];  // [4, 10240]
    const float* beta  = (const float*)d_in[4];  // [4, 10240]
    float* out = (float*)d_out;                  // [8192, 40, 256]

    cudaFuncSetAttribute(k_gemm_mma, cudaFuncAttributeMaxDynamicSharedMemorySize,
                         SMEM_MMA_BYTES);

    k_zero<<<(cN * cF + 255) / 256, 256>>>();
    k_wprep<<<cF, cF>>>(Wm);
    k_z<<<dim3(cB, cNBLK), 256>>>(inp, adj);
    k_gemm_mma<<<dim3((unsigned)(cM / 128), 2), 256, SMEM_MMA_BYTES>>>(out);
    k_stats<<<dim3(64, cN), 256>>>(out);
    k_finalize<<<cN, cF>>>(gamma, beta);
    k_norm<<<20480, 256>>>(out);
}

// round 14
// speedup vs baseline: 1.6512x; 1.0277x over previous
#include <cuda_runtime.h>
#include <cuda_bf16.h>
#include <cstdint>

constexpr int cB = 8192;
constexpr int cN = 40;
constexpr int cF = 256;
constexpr int cNBLK = 4;
constexpr int cBLK = 10;
constexpr long long cM = (long long)cB * cN;  // 327680 rows
constexpr float cEPS = 1e-5f;

// Scratch (device globals: allocation-free per harness rules).
__device__ __nv_bfloat16 g_zh[(size_t)cM * cF];   // 167 MB: z hi split
__device__ __nv_bfloat16 g_zl[(size_t)cM * cF];   // 167 MB: z lo split
__device__ __nv_bfloat16 g_wth[cF * cF];          // W^T hi: [n][k]
__device__ __nv_bfloat16 g_wtl[cF * cF];          // W^T lo: [n][k]
__device__ float g_sum[cN * cF];
__device__ float g_sumsq[cN * cF];
__device__ float g_scale[cN * cF];
__device__ float g_bias[cN * cF];

// ---------------------------------------------------------------------------
// helpers
// ---------------------------------------------------------------------------
__device__ __forceinline__ uint32_t smem_to_u32(const void* p) {
    uint32_t a;
    asm("{ .reg .u64 t; cvta.to.shared.u64 t, %1; cvt.u32.u64 %0, t; }"
        : "=r"(a) : "l"(p));
    return a;
}
#define SMEM_SWIZZLE_128B(byte_offset) ((byte_offset) ^ (((byte_offset) >> 3) & 0x70))

__device__ __forceinline__ void cp16(uint32_t dst, const void* src) {
    asm volatile("cp.async.ca.shared.global [%0], [%1], 16;"
                 :: "r"(dst), "l"(src) : "memory");
}
__device__ __forceinline__ void ldm_x4(uint32_t* r, uint32_t addr) {
    asm volatile("ldmatrix.sync.aligned.m8n8.x4.shared.b16 {%0,%1,%2,%3}, [%4];"
                 : "=r"(r[0]), "=r"(r[1]), "=r"(r[2]), "=r"(r[3]) : "r"(addr));
}
__device__ __forceinline__ void mma16816(float* c, const uint32_t* a,
                                         uint32_t b0, uint32_t b1) {
    asm volatile(
        "mma.sync.aligned.m16n8k16.row.col.f32.bf16.bf16.f32 "
        "{%0,%1,%2,%3}, {%4,%5,%6,%7}, {%8,%9}, {%0,%1,%2,%3};"
        : "+f"(c[0]), "+f"(c[1]), "+f"(c[2]), "+f"(c[3])
        : "r"(a[0]), "r"(a[1]), "r"(a[2]), "r"(a[3]), "r"(b0), "r"(b1));
}
// ldmatrix x4 address for a 16-row x 16-col(bf16) block at (row0, c16base*8
// bf16 cols) in a tile with 128-byte rows + SW128 swizzle.
__device__ __forceinline__ uint32_t frag_addr(uint32_t tile_base, int row0,
                                              int c16base, int lane) {
    int row = row0 + (lane & 7) + ((lane >> 3) & 1) * 8;
    int c16 = c16base + (lane >> 4);
    return tile_base + row * 128 + ((c16 ^ (row & 7)) * 16);
}

// ---------------------------------------------------------------------------
// k_zero: clear stat accumulators (graph replays must be idempotent)
// ---------------------------------------------------------------------------
__global__ void k_zero() {
    int i = blockIdx.x * blockDim.x + threadIdx.x;
    if (i < cN * cF) { g_sum[i] = 0.f; g_sumsq[i] = 0.f; }
}

// ---------------------------------------------------------------------------
// k_wprep: W[k][n] -> transposed bf16 hi/lo splits Wt[n][k]
// ---------------------------------------------------------------------------
__global__ void k_wprep(const float* __restrict__ W) {
    int n = blockIdx.x, k = threadIdx.x;
    float w = W[k * cF + n];
    __nv_bfloat16 hi = __float2bfloat16(w);
    __nv_bfloat16 lo = __float2bfloat16(w - __bfloat162float(hi));
    g_wth[n * cF + k] = hi;
    g_wtl[n * cF + k] = lo;
}

// ---------------------------------------------------------------------------
// k_z: z[b, s+r, k] = sum_j adj[b,s+r,s+j] * input[b,s+j,k], split to bf16
// hi/lo. One CTA per (batch, crop); input staged in smem, read once.
// ---------------------------------------------------------------------------
__global__ void __launch_bounds__(256) k_z(const float* __restrict__ inp,
                                           const float* __restrict__ adj) {
    const int b = blockIdx.x;
    const int s = blockIdx.y * cBLK;
    __shared__ float a[cBLK][cBLK];
    __shared__ float x[cBLK][cF];
    const int tid = threadIdx.x;

    if (tid < cBLK * cBLK)
        a[tid / cBLK][tid % cBLK] =
            adj[((size_t)b * cN + s + tid / cBLK) * cN + s + tid % cBLK];
    #pragma unroll
    for (int idx = tid; idx < cBLK * cF; idx += 256) {
        int j = idx >> 8, k = idx & 255;
        x[j][k] = inp[((size_t)b * cN + s + j) * cF + k];
    }
    __syncthreads();
    for (int idx = tid; idx < cBLK * (cF / 2); idx += 256) {
        int r = idx >> 7, k2 = (idx & 127) * 2;
        float acc0 = 0.f, acc1 = 0.f;
        #pragma unroll
        for (int j = 0; j < cBLK; j++) {
            acc0 = fmaf(a[r][j], x[j][k2], acc0);
            acc1 = fmaf(a[r][j], x[j][k2 + 1], acc1);
        }
        __nv_bfloat16 h0 = __float2bfloat16(acc0);
        __nv_bfloat16 h1 = __float2bfloat16(acc1);
        __nv_bfloat16 l0 = __float2bfloat16(acc0 - __bfloat162float(h0));
        __nv_bfloat16 l1 = __float2bfloat16(acc1 - __bfloat162float(h1));
        size_t off = ((size_t)b * cN + s + r) * cF + k2;
        __nv_bfloat162 hv; hv.x = h0; hv.y = h1;
        __nv_bfloat162 lv; lv.x = l0; lv.y = l1;
        *(__nv_bfloat162*)(g_zh + off) = hv;
        *(__nv_bfloat162*)(g_zl + off) = lv;
    }
}

// ---------------------------------------------------------------------------
// k_gemm_mma: y = z @ W via mma.sync bf16 3-pass split
//   (zh@Wh + zh@Wl + zl@Wh), fp32 accumulate.
// CTA: 128(M) x 128(N), 256 threads = 8 warps (2 M x 4 N), warp tile 64x32.
// K-loop: 8 chunks of 32, cp.async double-buffered (2 stages x 32 KB).
// Per stage, each 128-byte smem row packs [hi 64B | lo 64B] for one source
// row: c16 0-3 = hi k, c16 4-7 = lo k. SW128 swizzle, conflict-free ldmatrix.
// Grid (2, 2560): x = N-half so consecutive bids share the A tile in L2.
// ---------------------------------------------------------------------------
constexpr int STAGE_BYTES = 32768;   // A 16 KB + B 16 KB
constexpr int SM_BOFF = 16384;
constexpr int SMEM_MMA_BYTES = 2 * STAGE_BYTES;  // 64 KB

__device__ __forceinline__ void prefetch_stage(uint32_t st_base, size_t mbase,
                                               int nbase, int k0, int tid) {
    #pragma unroll
    for (int i = 0; i < 4; i++) {
        int idx = i * 256 + tid;          // 0..1023
        int r = idx >> 3, c16 = idx & 7;
        int kk = k0 + (c16 & 3) * 8;
        uint32_t soff = SMEM_SWIZZLE_128B(r * 128 + c16 * 16);
        const __nv_bfloat16* asrc = (c16 < 4) ? g_zh : g_zl;
        cp16(st_base + soff, asrc + (mbase + r) * cF + kk);
        const __nv_bfloat16* bsrc = (c16 < 4) ? g_wth : g_wtl;
        cp16(st_base + SM_BOFF + soff, bsrc + (size_t)(nbase + r) * cF + kk);
    }
}

__global__ void __launch_bounds__(256) k_gemm_mma(float* __restrict__ y) {
    extern __shared__ __align__(128) char smem[];
    const uint32_t sb = smem_to_u32(smem);
    const int tid = threadIdx.x;
    const int wid = tid >> 5, lane = tid & 31;
    const int wm = wid & 1, wn = wid >> 1;  // warp grid 2(M) x 4(N)
    const int nbase = blockIdx.x * 128;     // x = N-half (A reuse in L2)
    const size_t mbase = (size_t)blockIdx.y * 128;

    float C[4][4][4];
    #pragma unroll
    for (int mt = 0; mt < 4; mt++)
        #pragma unroll
        for (int nt = 0; nt < 4; nt++)
            #pragma unroll
            for (int i = 0; i < 4; i++) C[mt][nt][i] = 0.f;

    prefetch_stage(sb, mbase, nbase, 0, tid);
    asm volatile("cp.async.commit_group;" ::: "memory");

    for (int ci = 0; ci < 8; ci++) {
        if (ci + 1 < 8) {
            prefetch_stage(sb + ((ci + 1) & 1) * STAGE_BYTES, mbase, nbase,
                           (ci + 1) * 32, tid);
            asm volatile("cp.async.commit_group;" ::: "memory");
            asm volatile("cp.async.wait_group 1;" ::: "memory");
        } else {
            asm volatile("cp.async.wait_group 0;" ::: "memory");
        }
        __syncthreads();

        const uint32_t sA = sb + (ci & 1) * STAGE_BYTES;
        const uint32_t sB = sA + SM_BOFF;
        #pragma unroll
        for (int ks = 0; ks < 2; ks++) {
            const int ch = ks * 2, cl = 4 + ks * 2;
            uint32_t a[4][4], bh[2][4], bl[2][4];
            #pragma unroll
            for (int p = 0; p < 2; p++) {
                ldm_x4(bh[p], frag_addr(sB, wn * 32 + p * 16, ch, lane));
                ldm_x4(bl[p], frag_addr(sB, wn * 32 + p * 16, cl, lane));
            }
            // pass 1+2: A-hi against B-hi and B-lo
            #pragma unroll
            for (int mt = 0; mt < 4; mt++)
                ldm_x4(a[mt], frag_addr(sA, wm * 64 + mt * 16, ch, lane));
            #pragma unroll
            for (int mt = 0; mt < 4; mt++)
                #pragma unroll
                for (int nt = 0; nt < 4; nt++) {
                    int p = nt >> 1, q = nt & 1;
                    mma16816(C[mt][nt], a[mt], bh[p][q], bh[p][q + 2]);
                    mma16816(C[mt][nt], a[mt], bl[p][q], bl[p][q + 2]);
                }
            // pass 3: A-lo against B-hi
            #pragma unroll
            for (int mt = 0; mt < 4; mt++)
                ldm_x4(a[mt], frag_addr(sA, wm * 64 + mt * 16, cl, lane));
            #pragma unroll
            for (int mt = 0; mt < 4; mt++)
                #pragma unroll
                for (int nt = 0; nt < 4; nt++) {
                    int p = nt >> 1, q = nt & 1;
                    mma16816(C[mt][nt], a[mt], bh[p][q], bh[p][q + 2]);
                }
        }
        __syncthreads();  // compute done before this buffer is refilled
    }

    // Epilogue: c0,c1 = (row, col..col+1); c2,c3 = (row+8, col..col+1).
    #pragma unroll
    for (int mt = 0; mt < 4; mt++) {
        #pragma unroll
        for (int nt = 0; nt < 4; nt++) {
            size_t row = mbase + wm * 64 + mt * 16 + (lane >> 2);
            int col = nbase + wn * 32 + nt * 8 + (lane & 3) * 2;
            float2 v0 = make_float2(C[mt][nt][0], C[mt][nt][1]);
            float2 v1 = make_float2(C[mt][nt][2], C[mt][nt][3]);
            *(float2*)(y + row * cF + col) = v0;
            *(float2*)(y + (row + 8) * cF + col) = v1;
        }
    }
}

// ---------------------------------------------------------------------------
// k_stats: per-(n,f) sum / sum-of-squares over batch; spread atomics.
// ---------------------------------------------------------------------------
__global__ void __launch_bounds__(256) k_stats(const float* __restrict__ y) {
    const int n = blockIdx.y;
    const int f = threadIdx.x;
    const size_t b0 = (size_t)blockIdx.x * 128;
    float s = 0.f, q = 0.f;
    #pragma unroll 8
    for (int b = 0; b < 128; b++) {
        float v = y[((b0 + b) * cN + n) * cF + f];
        s += v;
        q = fmaf(v, v, q);
    }
    atomicAdd(&g_sum[n * cF + f], s);
    atomicAdd(&g_sumsq[n * cF + f], q);
}

// ---------------------------------------------------------------------------
// k_finalize: fold BN into per-column scale/bias.
// ---------------------------------------------------------------------------
__global__ void k_finalize(const float* __restrict__ gamma,
                           const float* __restrict__ beta) {
    const int n = blockIdx.x, f = threadIdx.x;
    const int idx = n * cF + f;
    const float invB = 1.0f / (float)cB;
    float mean = g_sum[idx] * invB;
    float var = fmaf(-mean, mean, g_sumsq[idx] * invB);
    float inv = rsqrtf(var + cEPS);
    float g = gamma[(n / cBLK) * (cN * cF) + idx];
    float bs = beta[idx] + beta[cN * cF + idx] + beta[2 * cN * cF + idx] +
               beta[3 * cN * cF + idx];
    float sc = inv * g;
    g_scale[idx] = sc;
    g_bias[idx] = fmaf(-mean, sc, bs);
}

// ---------------------------------------------------------------------------
// k_norm: out = out*scale + bias, in place, float4 grid-stride.
// ---------------------------------------------------------------------------
__global__ void __launch_bounds__(256) k_norm(float* __restrict__ out) {
    const size_t total4 = (size_t)cM * cF / 4;
    float4* o4 = (float4*)out;
    for (size_t i = (size_t)blockIdx.x * blockDim.x + threadIdx.x; i < total4;
         i += (size_t)gridDim.x * blockDim.x) {
        int c = (int)(i % (size_t)(cN * cF / 4)) * 4;
        float4 v = o4[i];
        float4 r;
        r.x = fmaf(v.x, g_scale[c + 0], g_bias[c + 0]);
        r.y = fmaf(v.y, g_scale[c + 1], g_bias[c + 1]);
        r.z = fmaf(v.z, g_scale[c + 2], g_bias[c + 2]);
        r.w = fmaf(v.w, g_scale[c + 3], g_bias[c + 3]);
        o4[i] = r;
    }
}

// ---------------------------------------------------------------------------
extern "C" void kernel_launch(void* const* d_in, const int* in_sizes, int n_in,
                              void* d_out, int out_size) {
    const float* inp   = (const float*)d_in[0];  // [8192, 40, 256]
    const float* adj   = (const float*)d_in[1];  // [8192, 40, 40]
    const float* Wm    = (const float*)d_in[2];  // [256, 256]
    const float* gamma = (const float*)d_in[3];  // [4, 10240]
    const float* beta  = (const float*)d_in[4];  // [4, 10240]
    float* out = (float*)d_out;                  // [8192, 40, 256]

    cudaFuncSetAttribute(k_gemm_mma, cudaFuncAttributeMaxDynamicSharedMemorySize,
                         SMEM_MMA_BYTES);

    k_zero<<<(cN * cF + 255) / 256, 256>>>();
    k_wprep<<<cF, cF>>>(Wm);
    k_z<<<dim3(cB, cNBLK), 256>>>(inp, adj);
    k_gemm_mma<<<dim3(2, (unsigned)(cM / 128)), 256, SMEM_MMA_BYTES>>>(out);
    k_stats<<<dim3(64, cN), 256>>>(out);
    k_finalize<<<cN, cF>>>(gamma, beta);
    k_norm<<<20480, 256>>>(out);
}